// round 11
// baseline (speedup 1.0000x reference)
#include <cuda_runtime.h>
#include <math.h>

// Problem constants
#define B_  8
#define A_  6
#define QS_ 32
#define KS_ 1024
#define NSPAT (256 * 64 * 64)              // 1048576 per (b, agent)
#define N4 (NSPAT / 4)                     // 262144 float4 per (b, agent)
#define OUT_MAIN ((size_t)B_ * A_ * NSPAT) // 50331648

#define PARTS 8                            // d-slices per batch
#define DSL (KS_ / PARTS)                  // 128 d per slice
#define ATTN_BLOCKS (B_ * PARTS)           // 64
#define COMBINE_BLOCKS (N4 * B_ / 256)     // 8192
#define TOTAL_BLOCKS (ATTN_BLOCKS + COMBINE_BLOCKS)

// Allocation-free scratch (device globals, zero-init; reset at end of run)
__device__ float g_attn[B_ * A_ * A_];               // softmaxed attention
__device__ float g_kp_part[B_ * PARTS * A_ * QS_];   // per-slice kp partials
__device__ float g_kb_part[B_ * PARTS * A_];         // per-slice kb partials
__device__ int   g_cnt[B_];                          // per-batch part arrivals
__device__ int   g_bflag[B_];                        // per-batch ready flag
__device__ int   g_done;                             // grid arrival counter

// --------------------------------------------------------------------------
// Single fused kernel.
//   Blocks 0..63  : attention partials (8 batches x 8 d-slices); the last-
//                   arriving slice per batch reduces + softmax + publishes.
//   Blocks 64+    : combine. CRITICAL: no v loads before the flag wait --
//                   keeps the attn blocks' loads uncontended (no priority
//                   inversion in the L1tex/LTS queues).
// --------------------------------------------------------------------------
__global__ void __launch_bounds__(256)
fused_kernel(const float* __restrict__ qu,    // [B, A, QS]
             const float* __restrict__ kmat,  // [B, A, KS]
             const float4* __restrict__ v,    // [B, A, NSPAT] as float4
             const float* __restrict__ Wm,    // [KS, QS]
             const float* __restrict__ bias,  // [KS]
             float4* __restrict__ out,        // [B, A, NSPAT] as float4
             float* __restrict__ out_tail,    // [B, A, A]
             int write_tail) {
    const int bid = blockIdx.x;
    const int tid = threadIdx.x;

    if (bid < ATTN_BLOCKS) {
        // ---------------- ATTENTION (8 batches x 8 d-slices) ----------------
        const int b    = bid >> 3;
        const int part = bid & 7;
        const int d0   = part * DSL;
        const int warp = tid >> 5;          // 0..7
        const int lane = tid & 31;

        __shared__ float s_k[A_][DSL];          // 3 KB
        __shared__ float s_part[8][A_][QS_];    // 6 KB
        __shared__ float s_kbp[A_];
        __shared__ float s_kp[A_ * QS_];
        __shared__ float s_kb[A_];
        __shared__ float s_attn[A_ * A_];
        __shared__ int   s_arrive;

        // Stage k slice: 6 rows x 128 floats = 192 float4
        if (tid < A_ * DSL / 4) {
            const int kk = tid >> 5, i = tid & 31;
            ((float4*)s_k[kk])[i] =
                ((const float4*)kmat)[((size_t)b * A_ + kk) * (KS_ / 4) + part * (DSL / 4) + i];
        }
        __syncthreads();

        // Warp w: 16 d-values, fully unrolled W loads (coalesced lines)
        {
            float acc[A_] = {0.f, 0.f, 0.f, 0.f, 0.f, 0.f};
            const int dl0 = warp * 16;
            #pragma unroll
            for (int i = 0; i < 16; i++) {
                const int dl = dl0 + i;
                const float wv = Wm[(size_t)(d0 + dl) * QS_ + lane];
                #pragma unroll
                for (int kk = 0; kk < A_; kk++)
                    acc[kk] = fmaf(s_k[kk][dl], wv, acc[kk]);
            }
            #pragma unroll
            for (int kk = 0; kk < A_; kk++)
                s_part[warp][kk][lane] = acc[kk];
        }

        // kb partial over the slice
        if (warp < A_) {
            float s = 0.f;
            #pragma unroll
            for (int i = 0; i < DSL / 32; i++) {
                const int dl = lane + 32 * i;
                s = fmaf(s_k[warp][dl], bias[d0 + dl], s);
            }
            #pragma unroll
            for (int off = 16; off; off >>= 1)
                s += __shfl_down_sync(0xffffffffu, s, off);
            if (lane == 0) s_kbp[warp] = s;
        }
        __syncthreads();

        // Publish slice partials
        if (tid < A_ * QS_) {
            const int kk = tid >> 5, j = tid & 31;
            float acc = 0.f;
            #pragma unroll
            for (int w = 0; w < 8; w++) acc += s_part[w][kk][j];
            g_kp_part[((size_t)(b * PARTS + part)) * (A_ * QS_) + tid] = acc;
        }
        if (tid < A_)
            g_kb_part[(b * PARTS + part) * A_ + tid] = s_kbp[tid];
        __threadfence();
        __syncthreads();

        if (tid == 0) s_arrive = atomicAdd(&g_cnt[b], 1);
        __syncthreads();

        if (s_arrive == PARTS - 1) {
            // -------- Reducer (one block per batch, fixed-order sums) --------
            if (tid < A_ * QS_) {
                float acc = 0.f;
                #pragma unroll
                for (int p = 0; p < PARTS; p++)
                    acc += g_kp_part[((size_t)(b * PARTS + p)) * (A_ * QS_) + tid];
                s_kp[tid] = acc;
            }
            if (tid < A_) {
                float acc = 0.f;
                #pragma unroll
                for (int p = 0; p < PARTS; p++)
                    acc += g_kb_part[(b * PARTS + p) * A_ + tid];
                s_kb[tid] = acc;
            }
            __syncthreads();

            if (tid < A_ * A_) {
                const int kk = tid / A_, qq = tid % A_;
                const float* __restrict__ qrow = qu + ((size_t)b * A_ + qq) * QS_;
                float s = s_kb[kk];
                #pragma unroll
                for (int j = 0; j < QS_; j++) s = fmaf(s_kp[kk * QS_ + j], qrow[j], s);
                s_attn[kk * A_ + qq] = s;
            }
            __syncthreads();

            if (tid < A_) {
                const int qq = tid;
                float m = -INFINITY;
                #pragma unroll
                for (int kk = 0; kk < A_; kk++) m = fmaxf(m, s_attn[kk * A_ + qq]);
                float e[A_], sum = 0.f;
                #pragma unroll
                for (int kk = 0; kk < A_; kk++) {
                    e[kk] = expf(s_attn[kk * A_ + qq] - m);
                    sum += e[kk];
                }
                const float inv = 1.f / sum;
                #pragma unroll
                for (int kk = 0; kk < A_; kk++) {
                    const float a = e[kk] * inv;
                    g_attn[b * 36 + kk * A_ + qq] = a;
                    if (write_tail) out_tail[b * 36 + kk * A_ + qq] = a;
                }
            }
            __syncthreads();
            if (tid == 0) {
                g_cnt[b] = 0;                 // reset for next replay
                __threadfence();              // g_attn visible before flag
                atomicExch(&g_bflag[b], 1);   // release
            }
        }

    } else {
        // ----------------------------- COMBINE -----------------------------
        const int chunk = bid - ATTN_BLOCKS;          // 0 .. 8191
        const int b = chunk >> 10;
        const int x = (chunk & 1023) * 256 + tid;     // 0 .. N4-1

        // Wait FIRST (no loads in flight -> attn loads uncontended).
        if (tid == 0) {
            int f;
            asm volatile("ld.acquire.gpu.global.b32 %0, [%1];"
                         : "=r"(f) : "l"(&g_bflag[b]) : "memory");
            while (f == 0) {
                __nanosleep(128);
                asm volatile("ld.acquire.gpu.global.b32 %0, [%1];"
                             : "=r"(f) : "l"(&g_bflag[b]) : "memory");
            }
        }
        __syncthreads();   // block-wide release; orders reads after acquire

        __shared__ float s_a[A_ * A_];
        if (tid < A_ * A_) s_a[tid] = g_attn[b * 36 + tid];
        __syncthreads();

        float4 vv[A_];
        #pragma unroll
        for (int kk = 0; kk < A_; kk++)
            vv[kk] = v[((size_t)(b * A_ + kk)) * N4 + x];

        #pragma unroll
        for (int qq = 0; qq < A_; qq++) {
            float4 o = make_float4(0.f, 0.f, 0.f, 0.f);
            #pragma unroll
            for (int kk = 0; kk < A_; kk++) {
                const float a = s_a[kk * A_ + qq];
                o.x = fmaf(a, vv[kk].x, o.x);
                o.y = fmaf(a, vv[kk].y, o.y);
                o.z = fmaf(a, vv[kk].z, o.z);
                o.w = fmaf(a, vv[kk].w, o.w);
            }
            out[((size_t)(b * A_ + qq)) * N4 + x] = o;
        }
    }

    // ---- per-run reset so graph replays are deterministic ----
    __syncthreads();
    if (tid == 0) {
        const int d = atomicAdd(&g_done, 1);
        if (d == TOTAL_BLOCKS - 1) {        // last block resets all state
            #pragma unroll
            for (int i = 0; i < B_; i++) g_bflag[i] = 0;
            g_done = 0;
            __threadfence();
        }
    }
}

extern "C" void kernel_launch(void* const* d_in, const int* in_sizes, int n_in,
                              void* d_out, int out_size) {
    const float* qu   = (const float*)d_in[0];   // [8,6,32]
    const float* kmat = (const float*)d_in[1];   // [8,6,1024]
    const float* v    = (const float*)d_in[2];   // [8,6,256,64,64]
    const float* Wm   = (const float*)d_in[3];   // [1024,32]
    const float* bias = (const float*)d_in[4];   // [1024]

    float* out = (float*)d_out;
    const int write_tail = ((size_t)out_size >= OUT_MAIN + (size_t)B_ * 36) ? 1 : 0;
    float* out_tail = out + OUT_MAIN;

    fused_kernel<<<TOTAL_BLOCKS, 256>>>(qu, kmat, (const float4*)v, Wm, bias,
                                        (float4*)out, out_tail, write_tail);
}